// round 2
// baseline (speedup 1.0000x reference)
#include <cuda_runtime.h>
#include <cuda_bf16.h>

// DifferentiableKendallTau: tau = sum_{i<j} tanh((p_j-p_i)*(t_j-t_i)/0.1) / (n*(n-1)/2)
// n = 8192. Single-kernel tiled all-pairs:
//  - shared tile packed float2{10*p, t}; per-thread packed (-10*pj, -tj)
//  - one add.rn.f32x2 per pair produces both diffs on one fma-pipe slot
//  - MUFU tanh.approx is the roofline binder (rt_SMSP=8)
//  - last-block-done finalize: no zero kernel, no finalize kernel

#define TILE 256

__device__ double       g_tau_sum;    // zero-initialized at module load; reset by last block
__device__ unsigned int g_count;      // ditto

__device__ __forceinline__ float fast_tanh(float x) {
    float y;
    asm("tanh.approx.f32 %0, %1;" : "=f"(y) : "f"(x));
    return y;
}

// (a.x + b.x, a.y + b.y) in a single packed f32x2 op, then multiply halves.
__device__ __forceinline__ float diff_prod(unsigned long long s2, unsigned long long negj) {
    unsigned long long d;
    asm("add.rn.f32x2 %0, %1, %2;" : "=l"(d) : "l"(s2), "l"(negj));
    float lo, hi;
    asm("mov.b64 {%0, %1}, %2;" : "=f"(lo), "=f"(hi) : "l"(d));
    return lo * hi;   // (10*pi - 10*pj) * (ti - tj) == 10 * pd * td
}

__global__ void __launch_bounds__(TILE, 8)
ktau_kernel(const float* __restrict__ pred,
            const float* __restrict__ target,
            int nt, float* __restrict__ out, double inv_pairs) {
    // Decode linear block id -> (bi, bj) with bi <= bj (upper-triangular tile pairs).
    int b = blockIdx.x;
    int bi = 0;
    int rem = b;
    while (rem >= nt - bi) { rem -= nt - bi; bi++; }
    int bj = bi + rem;

    __shared__ float2 sh[TILE];            // {10*p_i, t_i}
    __shared__ float  warp_sums[TILE / 32];

    int tid = threadIdx.x;

    sh[tid] = make_float2(10.0f * pred[bi * TILE + tid], target[bi * TILE + tid]);
    __syncthreads();

    int j = bj * TILE + tid;
    float2 nj = make_float2(-10.0f * pred[j], -target[j]);
    unsigned long long negj;
    asm("mov.b64 %0, {%1, %2};" : "=l"(negj) : "f"(nj.x), "f"(nj.y));

    const unsigned long long* sh64 = reinterpret_cast<const unsigned long long*>(sh);

    float acc0 = 0.0f, acc1 = 0.0f;

    if (bi != bj) {
        // Off-diagonal: every i in tile < every j. Unconditional 256-iter loop.
        #pragma unroll 8
        for (int i = 0; i < TILE; i += 2) {
            acc0 += fast_tanh(diff_prod(sh64[i],     negj));
            acc1 += fast_tanh(diff_prod(sh64[i + 1], negj));
        }
    } else {
        // Diagonal tile: strict i < j only (local i < tid).
        #pragma unroll 4
        for (int i = 0; i < tid; i++) {
            acc0 += fast_tanh(diff_prod(sh64[i], negj));
        }
    }

    float acc = acc0 + acc1;

    // Warp reduction.
    #pragma unroll
    for (int off = 16; off > 0; off >>= 1)
        acc += __shfl_xor_sync(0xFFFFFFFFu, acc, off);

    int lane = tid & 31;
    int wid  = tid >> 5;
    if (lane == 0) warp_sums[wid] = acc;
    __syncthreads();

    if (tid == 0) {
        double s = 0.0;
        #pragma unroll
        for (int w = 0; w < TILE / 32; w++) s += (double)warp_sums[w];
        atomicAdd(&g_tau_sum, s);
        __threadfence();
        unsigned int old = atomicAdd(&g_count, 1u);
        if (old == (unsigned int)gridDim.x - 1u) {
            // Last block: all partials are in g_tau_sum (fence-ordered before counts).
            double total = *((volatile double*)&g_tau_sum);
            out[0] = (float)(total * inv_pairs);
            // Reset for the next graph replay (deterministic: only this block runs here).
            g_tau_sum = 0.0;
            g_count   = 0u;
            __threadfence();
        }
    }
}

extern "C" void kernel_launch(void* const* d_in, const int* in_sizes, int n_in,
                              void* d_out, int out_size) {
    const float* pred   = (const float*)d_in[0];
    const float* target = (const float*)d_in[1];
    float* out = (float*)d_out;

    int n  = in_sizes[0];              // 8192
    int nt = n / TILE;                 // 32
    int nblocks = nt * (nt + 1) / 2;   // 528

    double n_pairs   = 0.5 * (double)n * (double)(n - 1);
    double inv_pairs = 1.0 / n_pairs;

    ktau_kernel<<<nblocks, TILE>>>(pred, target, nt, out, inv_pairs);
}